// round 3
// baseline (speedup 1.0000x reference)
#include <cuda_runtime.h>

// out[e] = dot(h[src[e]], h[dst[e]]), h: [N,128] fp32, E ~ 3.2M, N ~ 100K.
//
// Strategy: bucket edges by src node (bucket = 32 consecutive node ids).
// Main kernel: one block per bucket; bucket's 32 src rows (contiguous 16KB of h)
// are staged in SMEM; edges stream with dst gathered from L2.
// Cuts L2 row traffic ~1.8x vs fully random gather of both endpoints.

#define MAX_EDGES     3200000
#define MAX_BINS      4096
#define NODES_PER_BIN 32
#define F4_PER_ROW    32          // 128 floats = 32 float4
#define SH_STRIDE     33          // float4 stride per row (pad to kill conflicts)

__device__ int  g_counts[MAX_BINS];
__device__ int  g_offsets[MAX_BINS + 1];
__device__ int  g_cursor[MAX_BINS];
__device__ int4 g_edges[MAX_EDGES];   // {src, dst, edge_id, pad}

// ---------------------------------------------------------------- zero
__global__ void zero_counts_kernel(int nb) {
    int i = blockIdx.x * blockDim.x + threadIdx.x;
    if (i < nb) g_counts[i] = 0;
}

// ---------------------------------------------------------------- histogram
__global__ void hist_kernel(const int* __restrict__ src, int n_edges) {
    int i = blockIdx.x * blockDim.x + threadIdx.x;
    int stride = gridDim.x * blockDim.x;
    for (; i < n_edges; i += stride)
        atomicAdd(&g_counts[src[i] >> 5], 1);
}

// ---------------------------------------------------------------- scan (1 block)
#define SCAN_T 1024
__global__ void scan_kernel(int nb) {
    __shared__ int sh[SCAN_T];
    __shared__ int carry_sh;
    int tid = threadIdx.x;
    if (tid == 0) carry_sh = 0;
    __syncthreads();

    int nchunk = (nb + SCAN_T - 1) / SCAN_T;
    for (int c = 0; c < nchunk; c++) {
        int carry_in = carry_sh;
        __syncthreads();
        int i = c * SCAN_T + tid;
        int v = (i < nb) ? g_counts[i] : 0;
        sh[tid] = v;
        __syncthreads();
        // Hillis-Steele inclusive scan
        #pragma unroll
        for (int off = 1; off < SCAN_T; off <<= 1) {
            int t = (tid >= off) ? sh[tid - off] : 0;
            __syncthreads();
            sh[tid] += t;
            __syncthreads();
        }
        int incl = sh[tid];
        int excl = incl - v + carry_in;
        if (i < nb) {
            g_offsets[i] = excl;
            g_cursor[i]  = excl;
        }
        __syncthreads();
        if (tid == 0) carry_sh = carry_in + sh[SCAN_T - 1];
        __syncthreads();
    }
    if (tid == 0) g_offsets[nb] = carry_sh;
}

// ---------------------------------------------------------------- scatter
__global__ void scatter_kernel(const int* __restrict__ src,
                               const int* __restrict__ dst, int n_edges) {
    int i = blockIdx.x * blockDim.x + threadIdx.x;
    int stride = gridDim.x * blockDim.x;
    for (; i < n_edges; i += stride) {
        int s = src[i];
        int d = dst[i];
        int pos = atomicAdd(&g_cursor[s >> 5], 1);
        g_edges[pos] = make_int4(s, d, i, 0);
    }
}

// ---------------------------------------------------------------- main
__global__ void __launch_bounds__(256)
edge_dot_bucket_kernel(const float4* __restrict__ h4,
                       float* __restrict__ out, int n_nodes) {
    __shared__ float4 sh[NODES_PER_BIN * SH_STRIDE];   // ~16.9 KB

    const int b   = blockIdx.x;
    const int tid = threadIdx.x;
    const int base_node = b * NODES_PER_BIN;
    const int rows = min(NODES_PER_BIN, n_nodes - base_node);

    // Stage this bucket's src rows (contiguous in h) into SMEM, coalesced.
    const float4* __restrict__ srcp = h4 + (size_t)base_node * F4_PER_ROW;
    for (int idx = tid; idx < rows * F4_PER_ROW; idx += blockDim.x) {
        int r = idx >> 5, c = idx & 31;
        sh[r * SH_STRIDE + c] = srcp[idx];
    }
    __syncthreads();

    const int start = g_offsets[b];
    const int end   = g_offsets[b + 1];

    const int warp  = tid >> 5;
    const int lane  = tid & 31;
    const int group = lane >> 3;   // 0..3
    const int sub   = lane & 7;    // 0..7

    // 64 edges per block-iteration: 8 warps x 4 groups x 2 edges.
    for (int base = start; base < end; base += 64) {
        const int i0 = base + warp * 8 + group * 2;
        const int i1 = i0 + 1;
        const bool v0 = (i0 < end);
        const bool v1 = (i1 < end);

        int4 e0 = v0 ? g_edges[i0] : make_int4(base_node, 0, 0, 0);
        int4 e1 = v1 ? g_edges[i1] : make_int4(base_node, 0, 0, 0);

        const float4* __restrict__ a0p = &sh[(e0.x & 31) * SH_STRIDE];
        const float4* __restrict__ a1p = &sh[(e1.x & 31) * SH_STRIDE];
        const float4* __restrict__ b0p = h4 + (size_t)e0.y * F4_PER_ROW;
        const float4* __restrict__ b1p = h4 + (size_t)e1.y * F4_PER_ROW;

        // 8 independent global loads (dst rows) + 8 SMEM loads.
        float4 B00 = __ldg(&b0p[sub +  0]);
        float4 B01 = __ldg(&b0p[sub +  8]);
        float4 B02 = __ldg(&b0p[sub + 16]);
        float4 B03 = __ldg(&b0p[sub + 24]);
        float4 B10 = __ldg(&b1p[sub +  0]);
        float4 B11 = __ldg(&b1p[sub +  8]);
        float4 B12 = __ldg(&b1p[sub + 16]);
        float4 B13 = __ldg(&b1p[sub + 24]);

        float4 A00 = a0p[sub +  0];
        float4 A01 = a0p[sub +  8];
        float4 A02 = a0p[sub + 16];
        float4 A03 = a0p[sub + 24];
        float4 A10 = a1p[sub +  0];
        float4 A11 = a1p[sub +  8];
        float4 A12 = a1p[sub + 16];
        float4 A13 = a1p[sub + 24];

        float s0 = A00.x * B00.x;
        s0 = fmaf(A00.y, B00.y, s0); s0 = fmaf(A00.z, B00.z, s0); s0 = fmaf(A00.w, B00.w, s0);
        s0 = fmaf(A01.x, B01.x, s0); s0 = fmaf(A01.y, B01.y, s0);
        s0 = fmaf(A01.z, B01.z, s0); s0 = fmaf(A01.w, B01.w, s0);
        s0 = fmaf(A02.x, B02.x, s0); s0 = fmaf(A02.y, B02.y, s0);
        s0 = fmaf(A02.z, B02.z, s0); s0 = fmaf(A02.w, B02.w, s0);
        s0 = fmaf(A03.x, B03.x, s0); s0 = fmaf(A03.y, B03.y, s0);
        s0 = fmaf(A03.z, B03.z, s0); s0 = fmaf(A03.w, B03.w, s0);

        float s1 = A10.x * B10.x;
        s1 = fmaf(A10.y, B10.y, s1); s1 = fmaf(A10.z, B10.z, s1); s1 = fmaf(A10.w, B10.w, s1);
        s1 = fmaf(A11.x, B11.x, s1); s1 = fmaf(A11.y, B11.y, s1);
        s1 = fmaf(A11.z, B11.z, s1); s1 = fmaf(A11.w, B11.w, s1);
        s1 = fmaf(A12.x, B12.x, s1); s1 = fmaf(A12.y, B12.y, s1);
        s1 = fmaf(A12.z, B12.z, s1); s1 = fmaf(A12.w, B12.w, s1);
        s1 = fmaf(A13.x, B13.x, s1); s1 = fmaf(A13.y, B13.y, s1);
        s1 = fmaf(A13.z, B13.z, s1); s1 = fmaf(A13.w, B13.w, s1);

        // Reduce within each 8-lane group.
        s0 += __shfl_xor_sync(0xFFFFFFFFu, s0, 4);
        s0 += __shfl_xor_sync(0xFFFFFFFFu, s0, 2);
        s0 += __shfl_xor_sync(0xFFFFFFFFu, s0, 1);
        s1 += __shfl_xor_sync(0xFFFFFFFFu, s1, 4);
        s1 += __shfl_xor_sync(0xFFFFFFFFu, s1, 2);
        s1 += __shfl_xor_sync(0xFFFFFFFFu, s1, 1);

        if (v0 && sub == 0) out[e0.z] = s0;
        if (v1 && sub == 0) out[e1.z] = s1;
    }
}

// ---------------------------------------------------------------- launch
extern "C" void kernel_launch(void* const* d_in, const int* in_sizes, int n_in,
                              void* d_out, int out_size)
{
    const float4* h4  = (const float4*)d_in[0];
    const int*    src = (const int*)d_in[1];
    const int*    dst = (const int*)d_in[2];
    float*        out = (float*)d_out;

    const int n_edges = in_sizes[1];
    const int n_nodes = in_sizes[0] / 128;
    const int nb = (n_nodes + NODES_PER_BIN - 1) / NODES_PER_BIN;

    zero_counts_kernel<<<(nb + 255) / 256, 256>>>(nb);
    hist_kernel<<<2048, 256>>>(src, n_edges);
    scan_kernel<<<1, SCAN_T>>>(nb);
    scatter_kernel<<<2048, 256>>>(src, dst, n_edges);
    edge_dot_bucket_kernel<<<nb, 256>>>(h4, out, n_nodes);
}

// round 4
// speedup vs baseline: 2.3156x; 2.3156x over previous
#include <cuda_runtime.h>

// out[e] = dot(h[src[e]], h[dst[e]]); h: [N,128] fp32, E ~3.2M, int32 idx.
//
// Direct-gather design (R2) + persistent grid-stride warps + index prefetch.
// 8 lanes per edge, 4 edges per warp-iteration. Each lane: 4 float4 from src
// row + 4 from dst row (8 independent LDG.128 in flight). Interleaved mapping
// (f4 index = sub + 8*j) -> each LDG covers one dense 128B line per group.
// Next iteration's indices prefetched during current iteration's compute.

#define F4_PER_ROW 32   // 128 floats = 32 float4

__global__ void __launch_bounds__(256, 5)
edge_dot_kernel(const float4* __restrict__ h4,
                const int* __restrict__ src,
                const int* __restrict__ dst,
                float* __restrict__ out,
                int n_edges)
{
    const int lane  = threadIdx.x & 31;
    const int group = lane >> 3;       // 0..3: edge slot within warp
    const int sub   = lane & 7;        // 0..7: lane within edge group

    const int warp_id    = (blockIdx.x * blockDim.x + threadIdx.x) >> 5;
    const int n_warps    = (gridDim.x * blockDim.x) >> 5;
    const int e_stride   = n_warps * 4;

    int e = warp_id * 4 + group;

    // Prefetch first indices
    int s_pre = 0, d_pre = 0;
    if (e < n_edges) {
        s_pre = __ldg(&src[e]);
        d_pre = __ldg(&dst[e]);
    }

    for (; e < n_edges; e += e_stride) {
        const int s = s_pre;
        const int d = d_pre;

        // Prefetch next iteration's indices (overlaps with row loads below)
        const int e_next = e + e_stride;
        if (e_next < n_edges) {
            s_pre = __ldg(&src[e_next]);
            d_pre = __ldg(&dst[e_next]);
        }

        const float4* __restrict__ hs = h4 + (size_t)s * F4_PER_ROW;
        const float4* __restrict__ hd = h4 + (size_t)d * F4_PER_ROW;

        // 8 independent 16B loads -> 8 x 128B lines in flight per group
        float4 a0 = __ldg(&hs[sub +  0]);
        float4 a1 = __ldg(&hs[sub +  8]);
        float4 a2 = __ldg(&hs[sub + 16]);
        float4 a3 = __ldg(&hs[sub + 24]);
        float4 b0 = __ldg(&hd[sub +  0]);
        float4 b1 = __ldg(&hd[sub +  8]);
        float4 b2 = __ldg(&hd[sub + 16]);
        float4 b3 = __ldg(&hd[sub + 24]);

        float sum;
        sum = a0.x * b0.x;
        sum = fmaf(a0.y, b0.y, sum);
        sum = fmaf(a0.z, b0.z, sum);
        sum = fmaf(a0.w, b0.w, sum);
        sum = fmaf(a1.x, b1.x, sum);
        sum = fmaf(a1.y, b1.y, sum);
        sum = fmaf(a1.z, b1.z, sum);
        sum = fmaf(a1.w, b1.w, sum);
        sum = fmaf(a2.x, b2.x, sum);
        sum = fmaf(a2.y, b2.y, sum);
        sum = fmaf(a2.z, b2.z, sum);
        sum = fmaf(a2.w, b2.w, sum);
        sum = fmaf(a3.x, b3.x, sum);
        sum = fmaf(a3.y, b3.y, sum);
        sum = fmaf(a3.z, b3.z, sum);
        sum = fmaf(a3.w, b3.w, sum);

        // Reduce within 8-lane group
        sum += __shfl_xor_sync(0xFFFFFFFFu, sum, 4);
        sum += __shfl_xor_sync(0xFFFFFFFFu, sum, 2);
        sum += __shfl_xor_sync(0xFFFFFFFFu, sum, 1);

        if (sub == 0)
            out[e] = sum;
    }
}

extern "C" void kernel_launch(void* const* d_in, const int* in_sizes, int n_in,
                              void* d_out, int out_size)
{
    const float4* h4  = (const float4*)d_in[0];
    const int*    src = (const int*)d_in[1];
    const int*    dst = (const int*)d_in[2];
    float*        out = (float*)d_out;

    const int n_edges = in_sizes[1];

    // Persistent-ish grid: 5 blocks/SM x 148 SMs = 740 blocks, 256 threads.
    const int blocks = 740;
    edge_dot_kernel<<<blocks, 256>>>(h4, src, dst, out, n_edges);
}